// round 1
// baseline (speedup 1.0000x reference)
#include <cuda_runtime.h>

#define BB 4
#define TT 32
#define DD 256
#define NN 1024
#define GROUP 32      // CTAs per batch group
#define COLS 32       // G columns owned per CTA
#define NTHR 256      // threads in main kernel (8 warps)
#define CPW 4         // columns per warp
#define NWARP 8

// ---------------- device scratch (no allocation allowed) ----------------
__device__ float    g_xn[BB*TT*NN];      // relu(ln(x@E))
__device__ float    g_tn[BB*TT*NN];      // relu(ln(targets@E))
__device__ float    g_p[2][BB][NN];      // p1 / p2 exchange buffers
__device__ float    g_reason[BB*TT*NN];  // max(p1,p2,p3)
__device__ unsigned g_bar[BB*32];        // one padded barrier counter per group

// ---------------- helpers ----------------
__device__ __forceinline__ float blockSum256(float v, float* red) {
#pragma unroll
  for (int o = 16; o; o >>= 1) v += __shfl_xor_sync(0xffffffffu, v, o);
  int w = threadIdx.x >> 5, l = threadIdx.x & 31;
  __syncthreads();                 // protect red[] reuse across calls
  if (l == 0) red[w] = v;
  __syncthreads();
  float s = red[0];
#pragma unroll
  for (int i = 1; i < NWARP; ++i) s += red[i];
  return s;
}

// ---------------- kernel 1: neurons = relu(layernorm(X @ E)) ----------------
__global__ void __launch_bounds__(256) prep_kernel(const float* __restrict__ x_seq,
                                                   const float* __restrict__ targets,
                                                   const float* __restrict__ E) {
  __shared__ float xs[DD], ts[DD];
  __shared__ float red[NWARP];
  int row = blockIdx.x;            // b*TT + t, 0..127
  int tid = threadIdx.x;           // 256

  if (row == 0 && tid < BB) g_bar[tid * 32] = 0u;   // reset group barriers (runs before main kernel, stream-ordered)

  xs[tid] = x_seq[row*DD + tid];
  ts[tid] = targets[row*DD + tid];
  __syncthreads();

  float ax0=0,ax1=0,ax2=0,ax3=0, at0=0,at1=0,at2=0,at3=0;
  for (int k = 0; k < DD; ++k) {
    float xv = xs[k], tv = ts[k];
    const float* Er = E + k*NN + tid;
    float e0 = Er[0], e1 = Er[256], e2 = Er[512], e3 = Er[768];
    ax0 += xv*e0; ax1 += xv*e1; ax2 += xv*e2; ax3 += xv*e3;
    at0 += tv*e0; at1 += tv*e1; at2 += tv*e2; at3 += tv*e3;
  }

  // layernorm + relu for x row
  {
    float s1 = blockSum256(ax0+ax1+ax2+ax3, red);
    float s2 = blockSum256(ax0*ax0+ax1*ax1+ax2*ax2+ax3*ax3, red);
    float mu  = s1 * (1.0f/NN);
    float var = s2 * (1.0f/NN) - mu*mu;
    float inv = rsqrtf(var + 1e-5f);
    float* o = g_xn + row*NN + tid;
    o[0]   = fmaxf(0.f, (ax0-mu)*inv);
    o[256] = fmaxf(0.f, (ax1-mu)*inv);
    o[512] = fmaxf(0.f, (ax2-mu)*inv);
    o[768] = fmaxf(0.f, (ax3-mu)*inv);
  }
  // layernorm + relu for target row
  {
    float s1 = blockSum256(at0+at1+at2+at3, red);
    float s2 = blockSum256(at0*at0+at1*at1+at2*at2+at3*at3, red);
    float mu  = s1 * (1.0f/NN);
    float var = s2 * (1.0f/NN) - mu*mu;
    float inv = rsqrtf(var + 1e-5f);
    float* o = g_tn + row*NN + tid;
    o[0]   = fmaxf(0.f, (at0-mu)*inv);
    o[256] = fmaxf(0.f, (at1-mu)*inv);
    o[512] = fmaxf(0.f, (at2-mu)*inv);
    o[768] = fmaxf(0.f, (at3-mu)*inv);
  }
}

// ---------------- kernel 2: persistent scan ----------------
// CTA (b, part) owns G[:, part*32 .. part*32+31] of batch b, column-major in SMEM.
__global__ void __launch_bounds__(NTHR, 1) main_kernel() {
  extern __shared__ float sm[];
  float* sg = sm;                  // COLS * NN  (column-major: sg[c*NN + n])
  float* xb = sg + COLS*NN;        // 2 * NN ping-pong x_neuron vectors
  float* pb = xb + 2*NN;           // NN staged p vector
  float* tb = pb + NN;             // COLS staged 0.5*tn values

  int cta  = blockIdx.x;
  int b    = cta >> 5;
  int part = cta & 31;
  int mbase = part * COLS;
  int tid = threadIdx.x, w = tid >> 5, l = tid & 31;
  unsigned* barp = g_bar + b*32;

  // init G slice = 0.01 * I
  for (int i = tid; i < COLS*NN; i += NTHR) {
    int c = i >> 10, n = i & (NN-1);
    sg[i] = (n == mbase + c) ? 0.01f : 0.0f;
  }
  unsigned epoch = 0;
  __syncthreads();

  for (int t = 0; t < TT; ++t) {
    float* xc = xb + (t & 1)*NN;
    const float* xp = xb + ((t & 1)^1)*NN;   // previous step's x (for pending update)
    const float* gx = g_xn + (b*TT + t)*NN;
    for (int i = tid; i < NN; i += NTHR) xc[i] = gx[i];
    // pending update factor: tn at step t-1 is tgt_neurons[:, t]
    if (tid < COLS) tb[tid] = 0.5f * g_tn[(b*TT + t)*NN + mbase + tid];
    __syncthreads();

    const float4* xc4 = (const float4*)xc;
    const float4* xp4 = (const float4*)xp;
    float acc[CPW];
    float r0, r1, r2, r3;

    // ---- phase 1: apply pending rank-1 max-update (if t>0), compute p1 ----
    {
#pragma unroll
      for (int c = 0; c < CPW; ++c) acc[c] = 0.f;
      float4* gc[CPW];
      float tv[CPW];
#pragma unroll
      for (int c = 0; c < CPW; ++c) {
        gc[c] = (float4*)(sg + (w*CPW + c)*NN);
        tv[c] = tb[w*CPW + c];
      }
      if (t > 0) {
#pragma unroll
        for (int i = 0; i < 8; ++i) {
          int idx = l + 32*i;
          float4 xpv = xp4[idx];
          float4 xcv = xc4[idx];
#pragma unroll
          for (int c = 0; c < CPW; ++c) {
            float4 g = gc[c][idx];
            g.x = fmaxf(g.x, xpv.x*tv[c]);
            g.y = fmaxf(g.y, xpv.y*tv[c]);
            g.z = fmaxf(g.z, xpv.z*tv[c]);
            g.w = fmaxf(g.w, xpv.w*tv[c]);
            gc[c][idx] = g;
            acc[c] += xcv.x*g.x + xcv.y*g.y + xcv.z*g.z + xcv.w*g.w;
          }
        }
      } else {
#pragma unroll
        for (int i = 0; i < 8; ++i) {
          int idx = l + 32*i;
          float4 xcv = xc4[idx];
#pragma unroll
          for (int c = 0; c < CPW; ++c) {
            float4 g = gc[c][idx];
            acc[c] += xcv.x*g.x + xcv.y*g.y + xcv.z*g.z + xcv.w*g.w;
          }
        }
      }
#pragma unroll
      for (int c = 0; c < CPW; ++c)
#pragma unroll
        for (int o = 16; o; o >>= 1) acc[c] += __shfl_xor_sync(0xffffffffu, acc[c], o);
      if (l == 0) {
        float4 st; st.x = acc[0]; st.y = acc[1]; st.z = acc[2]; st.w = acc[3];
        *(float4*)(&g_p[0][b][mbase + w*CPW]) = st;
      }
      r0 = acc[0]; r1 = acc[1]; r2 = acc[2]; r3 = acc[3];
    }

    // ---- group barrier #1 ----
    epoch++;
    __syncthreads();
    if (tid == 0) {
      __threadfence();
      atomicAdd(barp, 1u);
      unsigned tgt = epoch * GROUP;
      while (*(volatile unsigned*)barp < tgt) { }
      __threadfence();
    }
    __syncthreads();

    // stage full p1
    {
      const float* gp = &g_p[0][b][0];
      for (int i = tid; i < NN; i += NTHR) pb[i] = gp[i];
    }
    __syncthreads();

    // ---- phase 2: p2 = p1 . G ----
    {
      const float4* p4 = (const float4*)pb;
#pragma unroll
      for (int c = 0; c < CPW; ++c) acc[c] = 0.f;
#pragma unroll
      for (int i = 0; i < 8; ++i) {
        int idx = l + 32*i;
        float4 pv = p4[idx];
#pragma unroll
        for (int c = 0; c < CPW; ++c) {
          float4 g = ((const float4*)(sg + (w*CPW + c)*NN))[idx];
          acc[c] += pv.x*g.x + pv.y*g.y + pv.z*g.z + pv.w*g.w;
        }
      }
#pragma unroll
      for (int c = 0; c < CPW; ++c)
#pragma unroll
        for (int o = 16; o; o >>= 1) acc[c] += __shfl_xor_sync(0xffffffffu, acc[c], o);
      if (l == 0) {
        float4 st; st.x = acc[0]; st.y = acc[1]; st.z = acc[2]; st.w = acc[3];
        *(float4*)(&g_p[1][b][mbase + w*CPW]) = st;
      }
      r0 = fmaxf(r0, acc[0]); r1 = fmaxf(r1, acc[1]);
      r2 = fmaxf(r2, acc[2]); r3 = fmaxf(r3, acc[3]);
    }

    // ---- group barrier #2 ----
    epoch++;
    __syncthreads();
    if (tid == 0) {
      __threadfence();
      atomicAdd(barp, 1u);
      unsigned tgt = epoch * GROUP;
      while (*(volatile unsigned*)barp < tgt) { }
      __threadfence();
    }
    __syncthreads();

    // stage full p2
    {
      const float* gp = &g_p[1][b][0];
      for (int i = tid; i < NN; i += NTHR) pb[i] = gp[i];
    }
    __syncthreads();

    // ---- phase 3: p3 = p2 . G  (column-local, no exchange needed) ----
    {
      const float4* p4 = (const float4*)pb;
#pragma unroll
      for (int c = 0; c < CPW; ++c) acc[c] = 0.f;
#pragma unroll
      for (int i = 0; i < 8; ++i) {
        int idx = l + 32*i;
        float4 pv = p4[idx];
#pragma unroll
        for (int c = 0; c < CPW; ++c) {
          float4 g = ((const float4*)(sg + (w*CPW + c)*NN))[idx];
          acc[c] += pv.x*g.x + pv.y*g.y + pv.z*g.z + pv.w*g.w;
        }
      }
#pragma unroll
      for (int c = 0; c < CPW; ++c)
#pragma unroll
        for (int o = 16; o; o >>= 1) acc[c] += __shfl_xor_sync(0xffffffffu, acc[c], o);
      r0 = fmaxf(r0, acc[0]); r1 = fmaxf(r1, acc[1]);
      r2 = fmaxf(r2, acc[2]); r3 = fmaxf(r3, acc[3]);
    }

    if (l == 0) {
      float4 st; st.x = r0; st.y = r1; st.z = r2; st.w = r3;
      *(float4*)(&g_reason[(b*TT + t)*NN + mbase + w*CPW]) = st;
    }
    __syncthreads();   // before next iteration re-stages xb/tb
  }
}

// ---------------- kernel 3: y = relu(reasoning @ Dy) ----------------
__global__ void __launch_bounds__(256) out_kernel(const float* __restrict__ Dy,
                                                  float* __restrict__ out) {
  __shared__ float rs[4*NN];
  int rbase = blockIdx.x * 4;      // grid 32 -> 128 rows
  int tid = threadIdx.x;           // 256 = one output column each
  for (int i = tid; i < 4*NN; i += 256) rs[i] = g_reason[rbase*NN + i];
  __syncthreads();
  float a0=0, a1=0, a2=0, a3=0;
#pragma unroll 4
  for (int n = 0; n < NN; ++n) {
    float dy = Dy[n*DD + tid];
    a0 += rs[n]        * dy;
    a1 += rs[NN + n]   * dy;
    a2 += rs[2*NN + n] * dy;
    a3 += rs[3*NN + n] * dy;
  }
  out[(rbase+0)*DD + tid] = fmaxf(a0, 0.f);
  out[(rbase+1)*DD + tid] = fmaxf(a1, 0.f);
  out[(rbase+2)*DD + tid] = fmaxf(a2, 0.f);
  out[(rbase+3)*DD + tid] = fmaxf(a3, 0.f);
}

// ---------------- launch ----------------
extern "C" void kernel_launch(void* const* d_in, const int* in_sizes, int n_in,
                              void* d_out, int out_size) {
  const float* x_seq   = (const float*)d_in[0];  // [4,32,256]
  const float* targets = (const float*)d_in[1];  // [4,32,256]
  const float* E       = (const float*)d_in[2];  // [256,1024]
  const float* Dy      = (const float*)d_in[3];  // [1024,256]
  float* out = (float*)d_out;                    // [4,32,256]

  int smem = (COLS*NN + 2*NN + NN + COLS) * (int)sizeof(float);  // ~140 KB
  cudaFuncSetAttribute(main_kernel, cudaFuncAttributeMaxDynamicSharedMemorySize, smem);

  prep_kernel<<<BB*TT, 256>>>(x_seq, targets, E);   // also resets barrier counters
  main_kernel<<<BB*GROUP, NTHR, smem>>>();
  out_kernel<<<32, 256>>>(Dy, out);
}

// round 3
// speedup vs baseline: 1.3938x; 1.3938x over previous
#include <cuda_runtime.h>

#define BB 4
#define TT 32
#define DD 256
#define NN 1024
#define GROUP 32      // CTAs per batch group
#define COLS 32       // G columns owned per CTA
#define NTHR 256      // threads in main kernel (8 warps)
#define CPW 4         // columns per warp (and per thread, register-resident)
#define JROWS 32      // row-groups per thread (n = l + 32*j)

// ---------------- device scratch (no allocation allowed) ----------------
__device__ float    g_xn[BB*TT*NN];      // relu(ln(x@E))
__device__ float    g_tn[BB*TT*NN];      // relu(ln(targets@E))
__device__ float    g_p[2][BB][NN];      // p1 / p2 exchange buffers
__device__ float    g_reason[BB*TT*NN];  // max(p1,p2,p3)
__device__ unsigned g_bar[BB*32];        // one padded barrier counter per group

// ---------------- barrier primitives (gpu-scope acq/rel, no MEMBAR.GPU) ----
__device__ __forceinline__ void bar_arrive(unsigned* p) {
  asm volatile("red.release.gpu.global.add.u32 [%0], %1;" :: "l"(p), "r"(1u) : "memory");
}
__device__ __forceinline__ unsigned bar_poll(unsigned* p) {
  unsigned v;
  asm volatile("ld.acquire.gpu.global.u32 %0, [%1];" : "=r"(v) : "l"(p) : "memory");
  return v;
}

// ---------------- kernel 1: neurons = relu(layernorm(X @ E)) ----------------
// 512 threads, 2 columns per thread, k-loop unrolled for MLP.
#define PW 16  // warps in prep
__device__ __forceinline__ float blockSum512(float v, float* red) {
#pragma unroll
  for (int o = 16; o; o >>= 1) v += __shfl_xor_sync(0xffffffffu, v, o);
  int w = threadIdx.x >> 5, l = threadIdx.x & 31;
  __syncthreads();
  if (l == 0) red[w] = v;
  __syncthreads();
  float s = red[0];
#pragma unroll
  for (int i = 1; i < PW; ++i) s += red[i];
  return s;
}

__global__ void __launch_bounds__(512) prep_kernel(const float* __restrict__ x_seq,
                                                   const float* __restrict__ targets,
                                                   const float* __restrict__ E) {
  __shared__ float xs[DD], ts[DD];
  __shared__ float red[PW];
  int row = blockIdx.x;            // b*TT + t, 0..127
  int tid = threadIdx.x;           // 0..511

  if (row == 0 && tid < BB) g_bar[tid * 32] = 0u;   // reset group barriers

  if (tid < DD) {
    xs[tid] = x_seq[row*DD + tid];
    ts[tid] = targets[row*DD + tid];
  }
  __syncthreads();

  float ax0=0, ax1=0, at0=0, at1=0;
#pragma unroll 8
  for (int k = 0; k < DD; ++k) {
    float xv = xs[k], tv = ts[k];
    const float* Er = E + k*NN + tid;
    float e0 = Er[0], e1 = Er[512];
    ax0 += xv*e0; ax1 += xv*e1;
    at0 += tv*e0; at1 += tv*e1;
  }

  {
    float s1 = blockSum512(ax0+ax1, red);
    float s2 = blockSum512(ax0*ax0+ax1*ax1, red);
    float mu  = s1 * (1.0f/NN);
    float var = s2 * (1.0f/NN) - mu*mu;
    float inv = rsqrtf(var + 1e-5f);
    float* o = g_xn + row*NN + tid;
    o[0]   = fmaxf(0.f, (ax0-mu)*inv);
    o[512] = fmaxf(0.f, (ax1-mu)*inv);
  }
  {
    float s1 = blockSum512(at0+at1, red);
    float s2 = blockSum512(at0*at0+at1*at1, red);
    float mu  = s1 * (1.0f/NN);
    float var = s2 * (1.0f/NN) - mu*mu;
    float inv = rsqrtf(var + 1e-5f);
    float* o = g_tn + row*NN + tid;
    o[0]   = fmaxf(0.f, (at0-mu)*inv);
    o[512] = fmaxf(0.f, (at1-mu)*inv);
  }
}

// ---------------- kernel 2: persistent scan, register-resident G ----------
// CTA (b, part) owns G[:, part*32 .. part*32+31] of batch b.
// Thread (w, l) owns columns part*32 + w*4 + {0..3}, rows n = l + 32*j, j=0..31.
__global__ void __launch_bounds__(NTHR, 1) main_kernel() {
  __shared__ float xb[2*NN];       // ping-pong x_neuron vectors
  __shared__ float pb[NN];         // staged p vector
  __shared__ float tb[COLS];       // staged 0.5*tn values

  int cta  = blockIdx.x;
  int b    = cta >> 5;
  int part = cta & 31;
  int mbase = part * COLS;
  int tid = threadIdx.x, w = tid >> 5, l = tid & 31;
  unsigned* barp = g_bar + b*32;

  // register-resident G slice: gr[j][c] = G[l+32*j][mbase + w*4 + c]
  float gr[JROWS][CPW];
  int cbase = mbase + w*CPW;
#pragma unroll
  for (int j = 0; j < JROWS; ++j) {
    int n = l + 32*j;
#pragma unroll
    for (int c = 0; c < CPW; ++c)
      gr[j][c] = (n == cbase + c) ? 0.01f : 0.0f;
  }

  unsigned epoch = 0;

  for (int t = 0; t < TT; ++t) {
    float* xc = xb + (t & 1)*NN;
    const float* xp = xb + ((t & 1)^1)*NN;
    const float* gx = g_xn + (b*TT + t)*NN;
    for (int i = tid; i < NN; i += NTHR) xc[i] = gx[i];
    if (tid < COLS) tb[tid] = 0.5f * g_tn[(b*TT + t)*NN + mbase + tid];
    __syncthreads();

    float acc0, acc1, acc2, acc3;
    float r0, r1, r2, r3;
    float tv0 = tb[w*CPW+0], tv1 = tb[w*CPW+1], tv2 = tb[w*CPW+2], tv3 = tb[w*CPW+3];

    // ---- phase 1: apply pending rank-1 max-update (t>0), compute p1 ----
    acc0 = acc1 = acc2 = acc3 = 0.f;
    if (t > 0) {
#pragma unroll
      for (int j = 0; j < JROWS; ++j) {
        float xpv = xp[l + 32*j];
        float xcv = xc[l + 32*j];
        gr[j][0] = fmaxf(gr[j][0], xpv*tv0);
        gr[j][1] = fmaxf(gr[j][1], xpv*tv1);
        gr[j][2] = fmaxf(gr[j][2], xpv*tv2);
        gr[j][3] = fmaxf(gr[j][3], xpv*tv3);
        acc0 += xcv*gr[j][0];
        acc1 += xcv*gr[j][1];
        acc2 += xcv*gr[j][2];
        acc3 += xcv*gr[j][3];
      }
    } else {
#pragma unroll
      for (int j = 0; j < JROWS; ++j) {
        float xcv = xc[l + 32*j];
        acc0 += xcv*gr[j][0];
        acc1 += xcv*gr[j][1];
        acc2 += xcv*gr[j][2];
        acc3 += xcv*gr[j][3];
      }
    }
#pragma unroll
    for (int o = 16; o; o >>= 1) {
      acc0 += __shfl_xor_sync(0xffffffffu, acc0, o);
      acc1 += __shfl_xor_sync(0xffffffffu, acc1, o);
      acc2 += __shfl_xor_sync(0xffffffffu, acc2, o);
      acc3 += __shfl_xor_sync(0xffffffffu, acc3, o);
    }
    if (l == 0) {
      float4 st; st.x = acc0; st.y = acc1; st.z = acc2; st.w = acc3;
      *(float4*)(&g_p[0][b][cbase]) = st;
    }
    r0 = acc0; r1 = acc1; r2 = acc2; r3 = acc3;

    // ---- group barrier #1 ----
    epoch++;
    __syncthreads();
    if (tid == 0) {
      bar_arrive(barp);
      unsigned tgt = epoch * GROUP;
      while (bar_poll(barp) < tgt) { }
    }
    __syncthreads();
    {
      const float* gp = &g_p[0][b][0];
      for (int i = tid; i < NN; i += NTHR) pb[i] = gp[i];
    }
    __syncthreads();

    // ---- phase 2: p2 = p1 . G ----
    acc0 = acc1 = acc2 = acc3 = 0.f;
#pragma unroll
    for (int j = 0; j < JROWS; ++j) {
      float pv = pb[l + 32*j];
      acc0 += pv*gr[j][0];
      acc1 += pv*gr[j][1];
      acc2 += pv*gr[j][2];
      acc3 += pv*gr[j][3];
    }
#pragma unroll
    for (int o = 16; o; o >>= 1) {
      acc0 += __shfl_xor_sync(0xffffffffu, acc0, o);
      acc1 += __shfl_xor_sync(0xffffffffu, acc1, o);
      acc2 += __shfl_xor_sync(0xffffffffu, acc2, o);
      acc3 += __shfl_xor_sync(0xffffffffu, acc3, o);
    }
    if (l == 0) {
      float4 st; st.x = acc0; st.y = acc1; st.z = acc2; st.w = acc3;
      *(float4*)(&g_p[1][b][cbase]) = st;
    }
    r0 = fmaxf(r0, acc0); r1 = fmaxf(r1, acc1);
    r2 = fmaxf(r2, acc2); r3 = fmaxf(r3, acc3);

    // ---- group barrier #2 ----
    epoch++;
    __syncthreads();
    if (tid == 0) {
      bar_arrive(barp);
      unsigned tgt = epoch * GROUP;
      while (bar_poll(barp) < tgt) { }
    }
    __syncthreads();
    {
      const float* gp = &g_p[1][b][0];
      for (int i = tid; i < NN; i += NTHR) pb[i] = gp[i];
    }
    __syncthreads();

    // ---- phase 3: p3 = p2 . G (column-local, no exchange) ----
    acc0 = acc1 = acc2 = acc3 = 0.f;
#pragma unroll
    for (int j = 0; j < JROWS; ++j) {
      float pv = pb[l + 32*j];
      acc0 += pv*gr[j][0];
      acc1 += pv*gr[j][1];
      acc2 += pv*gr[j][2];
      acc3 += pv*gr[j][3];
    }
#pragma unroll
    for (int o = 16; o; o >>= 1) {
      acc0 += __shfl_xor_sync(0xffffffffu, acc0, o);
      acc1 += __shfl_xor_sync(0xffffffffu, acc1, o);
      acc2 += __shfl_xor_sync(0xffffffffu, acc2, o);
      acc3 += __shfl_xor_sync(0xffffffffu, acc3, o);
    }
    r0 = fmaxf(r0, acc0); r1 = fmaxf(r1, acc1);
    r2 = fmaxf(r2, acc2); r3 = fmaxf(r3, acc3);

    if (l == 0) {
      float4 st; st.x = r0; st.y = r1; st.z = r2; st.w = r3;
      *(float4*)(&g_reason[(b*TT + t)*NN + cbase]) = st;
    }
    __syncthreads();   // before next iteration re-stages xb/tb
  }
}

// ---------------- kernel 3: y = relu(reasoning @ Dy) ----------------
__global__ void __launch_bounds__(256) out_kernel(const float* __restrict__ Dy,
                                                  float* __restrict__ out) {
  __shared__ float rs[2*NN];
  int rbase = blockIdx.x * 2;      // grid 64 -> 128 rows
  int tid = threadIdx.x;           // 256 = one output column each
  for (int i = tid; i < 2*NN; i += 256) rs[i] = g_reason[rbase*NN + i];
  __syncthreads();
  float a0=0, a1=0;
#pragma unroll 8
  for (int n = 0; n < NN; ++n) {
    float dy = Dy[n*DD + tid];
    a0 += rs[n]      * dy;
    a1 += rs[NN + n] * dy;
  }
  out[(rbase+0)*DD + tid] = fmaxf(a0, 0.f);
  out[(rbase+1)*DD + tid] = fmaxf(a1, 0.f);
}

// ---------------- launch ----------------
extern "C" void kernel_launch(void* const* d_in, const int* in_sizes, int n_in,
                              void* d_out, int out_size) {
  const float* x_seq   = (const float*)d_in[0];  // [4,32,256]
  const float* targets = (const float*)d_in[1];  // [4,32,256]
  const float* E       = (const float*)d_in[2];  // [256,1024]
  const float* Dy      = (const float*)d_in[3];  // [1024,256]
  float* out = (float*)d_out;                    // [4,32,256]

  prep_kernel<<<BB*TT, 512>>>(x_seq, targets, E);   // also resets barrier counters
  main_kernel<<<BB*GROUP, NTHR>>>();
  out_kernel<<<64, 256>>>(Dy, out);
}

// round 5
// speedup vs baseline: 1.4766x; 1.0594x over previous
#include <cuda_runtime.h>

#define BB 4
#define TT 32
#define DD 256
#define NN 1024
#define GROUP 32      // CTAs per batch group
#define COLS 32       // G columns owned per CTA
#define NTHR 512      // threads in main kernel (16 warps)
#define CPW 2         // columns per warp (register-resident)
#define JROWS 32      // row-groups per thread (n = l + 32*j)

// ---------------- device scratch ----------------
__device__ float    g_xn[BB*TT*NN];      // relu(ln(x@E))
__device__ float    g_tn[BB*TT*NN];      // relu(ln(targets@E))
__device__ float    g_p[2][BB][NN];      // p1 / p2 exchange buffers
__device__ float    g_reason[BB*TT*NN];  // max(p1,p2,p3)
__device__ unsigned g_bar[BB*32];        // padded barrier counter per group

// ---------------- barrier primitives ----------------
__device__ __forceinline__ void bar_arrive(unsigned* p) {
  asm volatile("red.release.gpu.global.add.u32 [%0], %1;" :: "l"(p), "r"(1u) : "memory");
}
__device__ __forceinline__ unsigned bar_poll(unsigned* p) {
  unsigned v;
  asm volatile("ld.acquire.gpu.global.u32 %0, [%1];" : "=r"(v) : "l"(p) : "memory");
  return v;
}

// ---------------- kernel 1: neurons = relu(layernorm(X @ E)) ----------------
#define PNW 8
__device__ __forceinline__ float blockSum256(float v, float* red) {
#pragma unroll
  for (int o = 16; o; o >>= 1) v += __shfl_xor_sync(0xffffffffu, v, o);
  int w = threadIdx.x >> 5, l = threadIdx.x & 31;
  __syncthreads();
  if (l == 0) red[w] = v;
  __syncthreads();
  float s = red[0];
#pragma unroll
  for (int i = 1; i < PNW; ++i) s += red[i];
  return s;
}

__global__ void __launch_bounds__(256) prep_kernel(const float* __restrict__ x_seq,
                                                   const float* __restrict__ targets,
                                                   const float* __restrict__ E) {
  __shared__ float xs[DD], ts[DD];
  __shared__ float red[PNW];
  int row = blockIdx.x;            // b*TT + t
  int tid = threadIdx.x;           // 0..255, handles cols 4*tid..4*tid+3

  if (row == 0 && tid < BB) g_bar[tid * 32] = 0u;   // reset group barriers

  if (tid < DD) {
    xs[tid] = x_seq[row*DD + tid];
    ts[tid] = targets[row*DD + tid];
  }
  __syncthreads();

  const float4* E4 = (const float4*)E;   // [256][256] float4
  float4 ax = make_float4(0.f,0.f,0.f,0.f);
  float4 at = make_float4(0.f,0.f,0.f,0.f);
#pragma unroll 8
  for (int k = 0; k < DD; ++k) {
    float xv = xs[k], tv = ts[k];
    float4 e = E4[k*256 + tid];
    ax.x += xv*e.x; ax.y += xv*e.y; ax.z += xv*e.z; ax.w += xv*e.w;
    at.x += tv*e.x; at.y += tv*e.y; at.z += tv*e.z; at.w += tv*e.w;
  }

  {
    float s1 = blockSum256(ax.x+ax.y+ax.z+ax.w, red);
    float s2 = blockSum256(ax.x*ax.x+ax.y*ax.y+ax.z*ax.z+ax.w*ax.w, red);
    float mu  = s1 * (1.0f/NN);
    float inv = rsqrtf(s2*(1.0f/NN) - mu*mu + 1e-5f);
    float4 o;
    o.x = fmaxf(0.f,(ax.x-mu)*inv); o.y = fmaxf(0.f,(ax.y-mu)*inv);
    o.z = fmaxf(0.f,(ax.z-mu)*inv); o.w = fmaxf(0.f,(ax.w-mu)*inv);
    ((float4*)(g_xn + row*NN))[tid] = o;
  }
  {
    float s1 = blockSum256(at.x+at.y+at.z+at.w, red);
    float s2 = blockSum256(at.x*at.x+at.y*at.y+at.z*at.z+at.w*at.w, red);
    float mu  = s1 * (1.0f/NN);
    float inv = rsqrtf(s2*(1.0f/NN) - mu*mu + 1e-5f);
    float4 o;
    o.x = fmaxf(0.f,(at.x-mu)*inv); o.y = fmaxf(0.f,(at.y-mu)*inv);
    o.z = fmaxf(0.f,(at.z-mu)*inv); o.w = fmaxf(0.f,(at.w-mu)*inv);
    ((float4*)(g_tn + row*NN))[tid] = o;
  }
}

// ---------------- kernel 2: persistent scan, register-resident G ----------
// CTA (b, part) owns G[:, part*32 .. +31]. 16 warps x 2 cols each.
// Thread (w, l): cols cbase = part*32 + w*2 + {0,1}, rows n = l + 32*j.
__global__ void __launch_bounds__(NTHR, 1) main_kernel() {
  __shared__ float xb[2*NN];       // ping-pong x_neuron vectors
  __shared__ float pb[NN];         // staged p vector
  __shared__ float tb[2][COLS];    // ping-pong 0.5*tn values

  int cta  = blockIdx.x;
  int b    = cta >> 5;
  int part = cta & 31;
  int mbase = part * COLS;
  int tid = threadIdx.x, w = tid >> 5, l = tid & 31;
  unsigned* barp = g_bar + b*32;
  int cbase = mbase + w*CPW;

  float gr0[JROWS], gr1[JROWS];
#pragma unroll
  for (int j = 0; j < JROWS; ++j) {
    int n = l + 32*j;
    gr0[j] = (n == cbase)     ? 0.01f : 0.0f;
    gr1[j] = (n == cbase + 1) ? 0.01f : 0.0f;
  }

  // stage step-0 inputs
  {
    const float* gx = g_xn + (b*TT)*NN;
    for (int i = tid; i < NN; i += NTHR) xb[i] = gx[i];
    if (tid < COLS) tb[0][tid] = 0.5f * g_tn[(b*TT)*NN + mbase + tid];
  }
  __syncthreads();

  unsigned epoch = 0;

  for (int t = 0; t < TT; ++t) {
    const float* xc = xb + (t & 1)*NN;
    const float* xp = xb + ((t & 1)^1)*NN;
    float tv0 = tb[t & 1][w*CPW + 0];
    float tv1 = tb[t & 1][w*CPW + 1];

    float acc0 = 0.f, acc1 = 0.f;
    float r0, r1;

    // ---- phase 1: apply pending rank-1 max-update (t>0), compute p1 ----
    if (t > 0) {
#pragma unroll
      for (int j = 0; j < JROWS; ++j) {
        float xpv = xp[l + 32*j];
        float xcv = xc[l + 32*j];
        gr0[j] = fmaxf(gr0[j], xpv*tv0);
        gr1[j] = fmaxf(gr1[j], xpv*tv1);
        acc0 += xcv*gr0[j];
        acc1 += xcv*gr1[j];
      }
    } else {
#pragma unroll
      for (int j = 0; j < JROWS; ++j) {
        float xcv = xc[l + 32*j];
        acc0 += xcv*gr0[j];
        acc1 += xcv*gr1[j];
      }
    }
#pragma unroll
    for (int o = 16; o; o >>= 1) {
      acc0 += __shfl_xor_sync(0xffffffffu, acc0, o);
      acc1 += __shfl_xor_sync(0xffffffffu, acc1, o);
    }
    if (l == 0) {
      float2 st; st.x = acc0; st.y = acc1;
      *(float2*)(&g_p[0][b][cbase]) = st;
    }
    r0 = acc0; r1 = acc1;

    // ---- group barrier #1 (prefetch next-step inputs in wait shadow) ----
    epoch++;
    __syncthreads();
    if (tid == 0) bar_arrive(barp);
    if (t + 1 < TT) {
      const float* gx2 = g_xn + (b*TT + t + 1)*NN;
      float* xn2 = xb + ((t + 1) & 1)*NN;
      for (int i = tid; i < NN; i += NTHR) xn2[i] = gx2[i];
      if (tid < COLS)
        tb[(t + 1) & 1][tid] = 0.5f * g_tn[(b*TT + t + 1)*NN + mbase + tid];
    }
    {
      unsigned tgt = epoch * GROUP;
      while (bar_poll(barp) < tgt) { }
    }
    {
      const float* gp = &g_p[0][b][0];
      for (int i = tid; i < NN; i += NTHR) pb[i] = __ldcg(gp + i);
    }
    __syncthreads();

    // ---- phase 2: p2 = p1 . G ----
    acc0 = 0.f; acc1 = 0.f;
#pragma unroll
    for (int j = 0; j < JROWS; ++j) {
      float pv = pb[l + 32*j];
      acc0 += pv*gr0[j];
      acc1 += pv*gr1[j];
    }
#pragma unroll
    for (int o = 16; o; o >>= 1) {
      acc0 += __shfl_xor_sync(0xffffffffu, acc0, o);
      acc1 += __shfl_xor_sync(0xffffffffu, acc1, o);
    }
    if (l == 0) {
      float2 st; st.x = acc0; st.y = acc1;
      *(float2*)(&g_p[1][b][cbase]) = st;
    }
    r0 = fmaxf(r0, acc0); r1 = fmaxf(r1, acc1);

    // ---- group barrier #2 ----
    epoch++;
    __syncthreads();
    if (tid == 0) bar_arrive(barp);
    {
      unsigned tgt = epoch * GROUP;
      while (bar_poll(barp) < tgt) { }
    }
    {
      const float* gp = &g_p[1][b][0];
      for (int i = tid; i < NN; i += NTHR) pb[i] = __ldcg(gp + i);
    }
    __syncthreads();

    // ---- phase 3: p3 = p2 . G (column-local) ----
    acc0 = 0.f; acc1 = 0.f;
#pragma unroll
    for (int j = 0; j < JROWS; ++j) {
      float pv = pb[l + 32*j];
      acc0 += pv*gr0[j];
      acc1 += pv*gr1[j];
    }
#pragma unroll
    for (int o = 16; o; o >>= 1) {
      acc0 += __shfl_xor_sync(0xffffffffu, acc0, o);
      acc1 += __shfl_xor_sync(0xffffffffu, acc1, o);
    }
    r0 = fmaxf(r0, acc0); r1 = fmaxf(r1, acc1);

    if (l == 0) {
      float2 st; st.x = r0; st.y = r1;
      *(float2*)(&g_reason[(b*TT + t)*NN + cbase]) = st;
    }
    // next iteration's inputs already staged & synced at barrier #1
  }
}

// ---------------- kernel 3: y = relu(reasoning @ Dy) ----------------
__global__ void __launch_bounds__(256) out_kernel(const float* __restrict__ Dy,
                                                  float* __restrict__ out) {
  __shared__ float rs[4*NN];
  int rbase = blockIdx.x * 4;      // grid 32 -> 128 rows
  int tid = threadIdx.x;
  int c4 = tid & 63;               // float4 column group (cols 4*c4..4*c4+3)
  int r  = tid >> 6;               // row within block (0..3)
  for (int i = tid; i < 4*NN; i += 256) rs[i] = g_reason[rbase*NN + i];
  __syncthreads();

  const float4* Dy4 = (const float4*)Dy;  // [1024][64] float4
  const float* rr = rs + r*NN;
  float4 a = make_float4(0.f,0.f,0.f,0.f);
#pragma unroll 8
  for (int n = 0; n < NN; ++n) {
    float4 d = Dy4[n*64 + c4];
    float pv = rr[n];
    a.x += pv*d.x; a.y += pv*d.y; a.z += pv*d.z; a.w += pv*d.w;
  }
  float4 o;
  o.x = fmaxf(a.x,0.f); o.y = fmaxf(a.y,0.f);
  o.z = fmaxf(a.z,0.f); o.w = fmaxf(a.w,0.f);
  ((float4*)(out + (rbase + r)*DD))[c4] = o;
}

// ---------------- launch ----------------
extern "C" void kernel_launch(void* const* d_in, const int* in_sizes, int n_in,
                              void* d_out, int out_size) {
  const float* x_seq   = (const float*)d_in[0];  // [4,32,256]
  const float* targets = (const float*)d_in[1];  // [4,32,256]
  const float* E       = (const float*)d_in[2];  // [256,1024]
  const float* Dy      = (const float*)d_in[3];  // [1024,256]
  float* out = (float*)d_out;                    // [4,32,256]

  prep_kernel<<<BB*TT, 256>>>(x_seq, targets, E);   // also resets barrier counters
  main_kernel<<<BB*GROUP, NTHR>>>();
  out_kernel<<<32, 256>>>(Dy, out);
}